// round 16
// baseline (speedup 1.0000x reference)
#include <cuda_runtime.h>

// Problem constants
#define BB    16
#define NTOK  4096
#define PPI   256
#define NE    8
#define CCAP  640

// Scratch (device globals; no allocation allowed)
__device__ float g_gate_pos[PPI * NE];
__device__ int   g_eidx[NTOK];
__device__ float g_gate[NTOK];        // prob at argmax; zeroed by rank if dropped
__device__ float g_psum[NE];
__device__ int   g_cnt[NE];
__device__ float g_tok[NTOK * NE];    // per-token per-co ReLU sums (ungated)

// ---------------------------------------------------------------------------
// Kernel 1: init — block 0: gate_pos table + zero psum;
//           blocks 1..63: bias pre-init of out (16 x 1000), off critical path.
// ---------------------------------------------------------------------------
__global__ void init_kernel(const float* __restrict__ gate_w,
                            const float* __restrict__ gate_b,
                            const float* __restrict__ lb,
                            float* __restrict__ out) {
    int bid = blockIdx.x;
    int t = threadIdx.x;
    if (bid != 0) {
        int idx = (bid - 1) * 256 + t;
        if (idx < BB * 1000) {
            int b = idx / 1000, j = idx - b * 1000;
            out[b * 1000 + j] = lb[j];
        }
        return;
    }
    if (t < NE) g_psum[t] = 0.f;
    int p = t;
    int r = p >> 4, c = p & 15;
    const float PI2 = 6.283185307179586f;
    float sgx = 0.f, s0x = 0.f, c0x = 0.f, s1x = 0.f, c1x = 0.f;
    for (int j = 0; j < 16; j++) {
        float gx = (float)(c * 16 + j) * (1.0f / 256.0f);
        sgx += gx;
        float a = PI2 * gx;
        float s_, c_;
        __sincosf(a, &s_, &c_);        s0x += s_; c0x += c_;
        __sincosf(2.f * a, &s_, &c_);  s1x += s_; c1x += c_;
    }
    float sgy = 0.f, s0y = 0.f, c0y = 0.f, s1y = 0.f, c1y = 0.f;
    for (int i = 0; i < 16; i++) {
        float gy = (float)(r * 16 + i) * (1.0f / 256.0f);
        sgy += gy;
        float a = PI2 * gy;
        float s_, c_;
        __sincosf(a, &s_, &c_);        s0y += s_; c0y += c_;
        __sincosf(2.f * a, &s_, &c_);  s1y += s_; c1y += c_;
    }
    float pcx = (c + 0.5f) / 16.f, pcy = (r + 0.5f) / 16.f;
    float spx, cpx, spy, cpy, s2px, c2px, s2py, c2py;
    __sincosf(PI2 * pcx, &spx, &cpx);
    __sincosf(PI2 * pcy, &spy, &cpy);
    __sincosf(2.f * PI2 * pcx, &s2px, &c2px);
    __sincosf(2.f * PI2 * pcy, &s2py, &c2py);
    float S[20];
    S[0]  = 16.f * sgx;    S[1]  = 16.f * sgy;
    S[2]  = 256.f * pcx;   S[3]  = 256.f * pcy;
    S[4]  = 16.f * s0x;    S[5]  = 16.f * c0x;
    S[6]  = 16.f * s0y;    S[7]  = 16.f * c0y;
    S[8]  = 256.f * spx;   S[9]  = 256.f * cpx;
    S[10] = 256.f * spy;   S[11] = 256.f * cpy;
    S[12] = 16.f * s1x;    S[13] = 16.f * c1x;
    S[14] = 16.f * s1y;    S[15] = 16.f * c1y;
    S[16] = 256.f * s2px;  S[17] = 256.f * c2px;
    S[18] = 256.f * s2py;  S[19] = 256.f * c2py;
    #pragma unroll
    for (int e = 0; e < NE; e++) {
        float acc = 0.f;
        #pragma unroll
        for (int cc = 0; cc < 20; cc++)
            acc += S[cc] * gate_w[e * 23 + 3 + cc];
        g_gate_pos[p * NE + e] = acc * (1.f / 256.f) + gate_b[e];
    }
}

// ---------------------------------------------------------------------------
// Kernel 2: megaconv — one block (128 thr) per patch.
// ALL 8 experts' weights preloaded during the staging phase (independent of
// the gate) -> the gate->weight-load serial chain and its barrier vanish.
// Single __syncthreads between staging and conv.
// ---------------------------------------------------------------------------
__global__ void __launch_bounds__(128, 8) megaconv_kernel(const float* __restrict__ X,
                                                          const float* __restrict__ ew,
                                                          const float* __restrict__ eb,
                                                          const float* __restrict__ gw) {
    __shared__ __align__(16) float sh_in[1080];    // 3 ci x 18 rows x 20 stride
    __shared__ __align__(16) float sh_wT[8 * 216]; // [e][kk][co] transposed, all experts
    __shared__ __align__(16) float sh_bA[64];      // [e][co] biases, all experts
    __shared__ float s_part[4][3];
    __shared__ float s_ws[4][8];                   // [warp][co]

    int n = blockIdx.x;
    int t = threadIdx.x;
    int b = n >> 8, p = n & 255;
    int r = p >> 4, c = p & 15;
    int lane = t & 31, wid = t >> 5;

    // halo zeros (disjoint from interior; same barrier interval)
    #pragma unroll
    for (int hz = 0; hz < 2; hz++) {
        int idx = t + hz * 128;
        if (idx < 204) {
            int ci = idx / 68;
            int rem = idx - ci * 68;
            int ii, jj;
            if (rem < 18)      { ii = 0;        jj = rem; }
            else if (rem < 36) { ii = 17;       jj = rem - 18; }
            else if (rem < 52) { ii = rem - 35; jj = 0; }
            else               { ii = rem - 51; jj = 17; }
            sh_in[ci * 360 + ii * 20 + jj] = 0.f;
        }
    }

    // preload ALL experts' weights (transposed [e][kk][co]) + biases —
    // independent of the gate; overlaps the X staging LDGs below.
    #pragma unroll
    for (int wv = 0; wv < 14; wv++) {
        int idx = wv * 128 + t;           // source-linear: e*216 + co*27 + kk
        if (idx < 8 * 216) {
            int e2 = idx / 216;
            int rem = idx - e2 * 216;
            int co = rem / 27, kk = rem - co * 27;
            sh_wT[(e2 * 27 + kk) * 8 + co] = ew[idx];
        }
    }
    if (t < 64) sh_bA[t] = eb[t];

    // fill interior + channel partial sums
    const float* Xb = X + (size_t)b * 3 * 65536 + (size_t)(r * 16) * 256 + c * 16;
    int col = t & 15, rw = t >> 4;
    float sc[3] = {0.f, 0.f, 0.f};
    #pragma unroll
    for (int ci = 0; ci < 3; ci++) {
        #pragma unroll
        for (int k = 0; k < 2; k++) {
            int row = rw + k * 8;
            float v = Xb[ci * 65536 + row * 256 + col];
            sh_in[ci * 360 + (row + 1) * 20 + (col + 1)] = v;
            sc[ci] += v;
        }
    }
    #pragma unroll
    for (int ci = 0; ci < 3; ci++) {
        float v = sc[ci];
        #pragma unroll
        for (int off = 16; off; off >>= 1)
            v += __shfl_xor_sync(0xffffffffu, v, off);
        if (lane == 0) s_part[wid][ci] = v;
    }
    __syncthreads();    // the ONLY staging barrier

    // per-warp gating (redundant across warps; no extra barrier)
    float S0 = s_part[0][0] + s_part[1][0] + s_part[2][0] + s_part[3][0];
    float S1 = s_part[0][1] + s_part[1][1] + s_part[2][1] + s_part[3][1];
    float S2 = s_part[0][2] + s_part[1][2] + s_part[2][2] + s_part[3][2];
    float lg = -1e30f;
    if (lane < NE) {
        lg = (S0 * gw[lane * 23 + 0] + S1 * gw[lane * 23 + 1] +
              S2 * gw[lane * 23 + 2]) * (1.f / 256.f)
             + g_gate_pos[p * NE + lane];
    }
    float m = lg;
    #pragma unroll
    for (int off = 4; off; off >>= 1)
        m = fmaxf(m, __shfl_xor_sync(0xffffffffu, m, off));
    float pe = (lane < NE) ? expf(lg - m) : 0.f;
    float sum = pe;
    #pragma unroll
    for (int off = 4; off; off >>= 1)
        sum += __shfl_xor_sync(0xffffffffu, sum, off);
    unsigned mk = __ballot_sync(0xffffffffu, lg == m) & 0xFFu;
    int e = __ffs(mk) - 1;      // uniform across block
    if (wid == 0) {
        if (lane < NE) atomicAdd(&g_psum[lane], pe / sum);
        if (lane == 0) { g_eidx[n] = e; g_gate[n] = 1.0f / sum; }
    }

    // conv: thread = 2x2 pixel block x 4 output channels; ci-outer
    int cog = t >> 6;
    int pb = t & 63;
    int R = (pb >> 3) * 2, C = (pb & 7) * 2;
    const float* wbase = &sh_wT[e * 216];

    float4 b4 = ((const float4*)sh_bA)[e * 2 + cog];
    float acc[2][2][4];
    #pragma unroll
    for (int py = 0; py < 2; py++)
        #pragma unroll
        for (int px = 0; px < 2; px++) {
            acc[py][px][0] = b4.x; acc[py][px][1] = b4.y;
            acc[py][px][2] = b4.z; acc[py][px][3] = b4.w;
        }

    #pragma unroll
    for (int ci = 0; ci < 3; ci++) {
        float in_f[4][4];
        #pragma unroll
        for (int rr = 0; rr < 4; rr++) {
            const float* base = &sh_in[ci * 360 + (R + rr) * 20 + C];
            float2 u0 = *(const float2*)(base);
            float2 u1 = *(const float2*)(base + 2);
            in_f[rr][0] = u0.x; in_f[rr][1] = u0.y;
            in_f[rr][2] = u1.x; in_f[rr][3] = u1.y;
        }
        #pragma unroll
        for (int dy = 0; dy < 3; dy++)
            #pragma unroll
            for (int dx = 0; dx < 3; dx++) {
                int kk = ci * 9 + dy * 3 + dx;
                float4 w4 = *(const float4*)(wbase + kk * 8 + cog * 4);
                #pragma unroll
                for (int py = 0; py < 2; py++)
                    #pragma unroll
                    for (int px = 0; px < 2; px++) {
                        float iv = in_f[dy + py][dx + px];
                        acc[py][px][0] = fmaf(w4.x, iv, acc[py][px][0]);
                        acc[py][px][1] = fmaf(w4.y, iv, acc[py][px][1]);
                        acc[py][px][2] = fmaf(w4.z, iv, acc[py][px][2]);
                        acc[py][px][3] = fmaf(w4.w, iv, acc[py][px][3]);
                    }
            }
    }

    float v[4];
    #pragma unroll
    for (int co = 0; co < 4; co++)
        v[co] = fmaxf(acc[0][0][co], 0.f) + fmaxf(acc[0][1][co], 0.f) +
                fmaxf(acc[1][0][co], 0.f) + fmaxf(acc[1][1][co], 0.f);

    // butterfly: fold co into lane bits 4,3, reduce remaining 8 lanes
    float s0, s1, o0, o1;
    if (lane & 16) { s0 = v[2]; s1 = v[3]; o0 = v[0]; o1 = v[1]; }
    else           { s0 = v[0]; s1 = v[1]; o0 = v[2]; o1 = v[3]; }
    s0 += __shfl_xor_sync(0xffffffffu, o0, 16);
    s1 += __shfl_xor_sync(0xffffffffu, o1, 16);
    float s, o;
    if (lane & 8) { s = s1; o = s0; } else { s = s0; o = s1; }
    s += __shfl_xor_sync(0xffffffffu, o, 8);
    s += __shfl_xor_sync(0xffffffffu, s, 4);
    s += __shfl_xor_sync(0xffffffffu, s, 2);
    s += __shfl_xor_sync(0xffffffffu, s, 1);
    if ((lane & 7) == 0) {
        int co = cog * 4 + ((lane >> 4) & 1) * 2 + ((lane >> 3) & 1);
        s_ws[wid][co] = s;
    }
    __syncthreads();
    if (t < 8) {
        float tot = (t < 4) ? (s_ws[0][t] + s_ws[1][t])
                            : (s_ws[2][t] + s_ws[3][t]);
        g_tok[n * 8 + t] = tot;
    }
}

// ---------------------------------------------------------------------------
// Kernel 3: rank + aux only. 1 block, 256 threads.
// ---------------------------------------------------------------------------
__global__ void rank_kernel(float* __restrict__ out, int out_size) {
    __shared__ int se[NTOK];
    int t = threadIdx.x;

    for (int i = t; i < NTOK; i += 256) se[i] = g_eidx[i];
    __syncthreads();
    int w = t >> 5, lane = t & 31;
    int base = 0;
    #pragma unroll 4
    for (int tt = 0; tt < NTOK / 32; tt++) {
        int idx = tt * 32 + lane;
        int e = se[idx];
        unsigned mask = __ballot_sync(0xffffffffu, e == w);
        if (e == w) {
            int rank = base + __popc(mask & ((1u << lane) - 1u));
            if (rank >= CCAP) g_gate[idx] = 0.f;
        }
        base += __popc(mask);
    }
    if (lane == 0) g_cnt[w] = base;
    __syncthreads();
    if (t == 0) {
        float aux = 0.f;
        #pragma unroll
        for (int e = 0; e < NE; e++) {
            float f = fminf((float)g_cnt[e], (float)CCAP) * (1.f / (float)NTOK);
            aux += f * (g_psum[e] * (1.f / (float)NTOK));
        }
        out[out_size - 1] = 8.f * aux;
    }
}

// ---------------------------------------------------------------------------
// Kernel 4: k-split classifier GEMM, 16-way k-split.
// grid (8 j-tiles, 4 batch-quads, 16 k-slices of 32) = 512 blocks x 128 thr.
// ---------------------------------------------------------------------------
__global__ void __launch_bounds__(128) linear_kernel(const float* __restrict__ lw,
                                                     float* __restrict__ out) {
    __shared__ __align__(16) float fs4[32][4];
    int bx = blockIdx.x, by = blockIdx.y, bz = blockIdx.z;
    int t = threadIdx.x;
    int k0 = bz * 32;

    {
        int kl = t & 31;
        int bq = t >> 5;
        int idx = k0 + kl;
        int co = idx >> 6;
        int cell = idx & 63;
        int py = cell >> 3, px = cell & 7;
        int bb = by * 4 + bq;
        float acc = 0.f;
        #pragma unroll
        for (int dy = 0; dy < 2; dy++)
            #pragma unroll
            for (int dx = 0; dx < 2; dx++) {
                int n = bb * 256 + (2 * py + dy) * 16 + (2 * px + dx);
                acc += g_tok[n * 8 + co] * g_gate[n];
            }
        fs4[kl][bq] = acc * (1.f / 1024.f);
    }
    __syncthreads();

    int j = bx * 128 + t;
    if (j < 1000) {
        const float* wp = lw + (size_t)k0 * 1000 + j;
        float a0 = 0.f, a1 = 0.f, a2 = 0.f, a3 = 0.f;
        #pragma unroll
        for (int k = 0; k < 32; k++) {
            float w = wp[(size_t)k * 1000];
            float4 f = *(const float4*)fs4[k];
            a0 = fmaf(w, f.x, a0);
            a1 = fmaf(w, f.y, a1);
            a2 = fmaf(w, f.z, a2);
            a3 = fmaf(w, f.w, a3);
        }
        int ob = by * 4;
        atomicAdd(&out[(ob + 0) * 1000 + j], a0);
        atomicAdd(&out[(ob + 1) * 1000 + j], a1);
        atomicAdd(&out[(ob + 2) * 1000 + j], a2);
        atomicAdd(&out[(ob + 3) * 1000 + j], a3);
    }
}

// ---------------------------------------------------------------------------
extern "C" void kernel_launch(void* const* d_in, const int* in_sizes, int n_in,
                              void* d_out, int out_size) {
    const float* X  = (const float*)d_in[0];
    const float* ew = (const float*)d_in[1];
    const float* eb = (const float*)d_in[2];
    const float* gw = (const float*)d_in[3];
    const float* gb = (const float*)d_in[4];
    const float* lw = (const float*)d_in[5];
    const float* lb = (const float*)d_in[6];
    float* out = (float*)d_out;

    init_kernel<<<64, 256>>>(gw, gb, lb, out);
    megaconv_kernel<<<NTOK, 128>>>(X, ew, eb, gw);
    rank_kernel<<<1, 256>>>(out, out_size);
    dim3 g(8, 4, 16);
    linear_kernel<<<g, 128>>>(lw, out);
}

// round 17
// speedup vs baseline: 1.2541x; 1.2541x over previous
#include <cuda_runtime.h>

// Problem constants
#define BB    16
#define NTOK  4096
#define PPI   256
#define NE    8
#define CCAP  640

// Scratch (device globals; no allocation allowed)
__device__ float g_gate_pos[PPI * NE];
__device__ int   g_eidx[NTOK];
__device__ float g_gate[NTOK];        // prob at argmax; zeroed by rank if dropped
__device__ float g_psum[NE];
__device__ int   g_cnt[NE];
__device__ float g_tok[NTOK * NE];    // per-token per-co ReLU sums (ungated)

// ---------------------------------------------------------------------------
// Kernel 1: init — blocks 0..31: gate_pos, ONE WARP PER PATCH POSITION
// (lanes 0-15 x-series, lanes 16-31 y-series, shfl-xor reduce, lanes 0-7
// finish one expert each). Blocks 32..95: out bias pre-init (+psum zero).
// ---------------------------------------------------------------------------
__global__ void __launch_bounds__(256) init_kernel(const float* __restrict__ gate_w,
                                                   const float* __restrict__ gate_b,
                                                   const float* __restrict__ lb,
                                                   float* __restrict__ out) {
    int bid = blockIdx.x;
    int t = threadIdx.x;
    const float PI2 = 6.283185307179586f;

    if (bid >= 32) {
        int idx = (bid - 32) * 256 + t;
        if (idx < BB * 1000) {
            int b = idx / 1000, j = idx - b * 1000;
            out[b * 1000 + j] = lb[j];
        }
        if (bid == 32 && t < NE) g_psum[t] = 0.f;
        return;
    }

    int wid = t >> 5, lane = t & 31;
    int p = bid * 8 + wid;
    int r = p >> 4, c = p & 15;

    // lanes 0-15: x-series term j=lane; lanes 16-31: y-series term i=lane-16
    int base = (lane < 16) ? c : r;
    int i16 = lane & 15;
    float g = (float)(base * 16 + i16) * (1.0f / 256.0f);
    float sA, cA, sB, cB;
    __sincosf(PI2 * g, &sA, &cA);
    __sincosf(2.f * PI2 * g, &sB, &cB);

    // reduce the 5 values within each 16-lane half (xor offsets stay in-half)
    #pragma unroll
    for (int off = 8; off; off >>= 1) {
        g  += __shfl_xor_sync(0xffffffffu, g,  off);
        sA += __shfl_xor_sync(0xffffffffu, sA, off);
        cA += __shfl_xor_sync(0xffffffffu, cA, off);
        sB += __shfl_xor_sync(0xffffffffu, sB, off);
        cB += __shfl_xor_sync(0xffffffffu, cB, off);
    }
    // x-sums live in lanes 0-15, y-sums in lanes 16-31; broadcast both
    float sgx = __shfl_sync(0xffffffffu, g,  0);
    float s0x = __shfl_sync(0xffffffffu, sA, 0);
    float c0x = __shfl_sync(0xffffffffu, cA, 0);
    float s1x = __shfl_sync(0xffffffffu, sB, 0);
    float c1x = __shfl_sync(0xffffffffu, cB, 0);
    float sgy = __shfl_sync(0xffffffffu, g,  16);
    float s0y = __shfl_sync(0xffffffffu, sA, 16);
    float c0y = __shfl_sync(0xffffffffu, cA, 16);
    float s1y = __shfl_sync(0xffffffffu, sB, 16);
    float c1y = __shfl_sync(0xffffffffu, cB, 16);

    if (lane < NE) {
        float pcx = (c + 0.5f) / 16.f, pcy = (r + 0.5f) / 16.f;
        float spx, cpx, spy, cpy, s2px, c2px, s2py, c2py;
        __sincosf(PI2 * pcx, &spx, &cpx);
        __sincosf(PI2 * pcy, &spy, &cpy);
        __sincosf(2.f * PI2 * pcx, &s2px, &c2px);
        __sincosf(2.f * PI2 * pcy, &s2py, &c2py);
        float S[20];
        S[0]  = 16.f * sgx;    S[1]  = 16.f * sgy;
        S[2]  = 256.f * pcx;   S[3]  = 256.f * pcy;
        S[4]  = 16.f * s0x;    S[5]  = 16.f * c0x;
        S[6]  = 16.f * s0y;    S[7]  = 16.f * c0y;
        S[8]  = 256.f * spx;   S[9]  = 256.f * cpx;
        S[10] = 256.f * spy;   S[11] = 256.f * cpy;
        S[12] = 16.f * s1x;    S[13] = 16.f * c1x;
        S[14] = 16.f * s1y;    S[15] = 16.f * c1y;
        S[16] = 256.f * s2px;  S[17] = 256.f * c2px;
        S[18] = 256.f * s2py;  S[19] = 256.f * c2py;
        int e = lane;
        float acc = 0.f;
        #pragma unroll
        for (int cc = 0; cc < 20; cc++)
            acc += S[cc] * gate_w[e * 23 + 3 + cc];
        g_gate_pos[p * NE + e] = acc * (1.f / 256.f) + gate_b[e];
    }
}

// ---------------------------------------------------------------------------
// Kernel 2: megaconv — one block (128 thr) per patch. EXACT R15 core (frozen).
// ---------------------------------------------------------------------------
__global__ void __launch_bounds__(128, 8) megaconv_kernel(const float* __restrict__ X,
                                                          const float* __restrict__ ew,
                                                          const float* __restrict__ eb,
                                                          const float* __restrict__ gw) {
    __shared__ __align__(16) float sh_in[1080];   // 3 ci x 18 rows x 20 stride
    __shared__ __align__(16) float sh_wT[216];    // [k][co] transposed
    __shared__ __align__(16) float sh_b[8];
    __shared__ float s_part[4][3];
    __shared__ float s_ws[4][8];                  // [warp][co]

    int n = blockIdx.x;
    int t = threadIdx.x;
    int b = n >> 8, p = n & 255;
    int r = p >> 4, c = p & 15;
    int lane = t & 31, wid = t >> 5;

    // halo zeros (disjoint from interior; same barrier interval)
    #pragma unroll
    for (int hz = 0; hz < 2; hz++) {
        int idx = t + hz * 128;
        if (idx < 204) {
            int ci = idx / 68;
            int rem = idx - ci * 68;
            int ii, jj;
            if (rem < 18)      { ii = 0;        jj = rem; }
            else if (rem < 36) { ii = 17;       jj = rem - 18; }
            else if (rem < 52) { ii = rem - 35; jj = 0; }
            else               { ii = rem - 51; jj = 17; }
            sh_in[ci * 360 + ii * 20 + jj] = 0.f;
        }
    }

    // fill interior + channel partial sums
    const float* Xb = X + (size_t)b * 3 * 65536 + (size_t)(r * 16) * 256 + c * 16;
    int col = t & 15, rw = t >> 4;
    float sc[3] = {0.f, 0.f, 0.f};
    #pragma unroll
    for (int ci = 0; ci < 3; ci++) {
        #pragma unroll
        for (int k = 0; k < 2; k++) {
            int row = rw + k * 8;
            float v = Xb[ci * 65536 + row * 256 + col];
            sh_in[ci * 360 + (row + 1) * 20 + (col + 1)] = v;
            sc[ci] += v;
        }
    }
    #pragma unroll
    for (int ci = 0; ci < 3; ci++) {
        float v = sc[ci];
        #pragma unroll
        for (int off = 16; off; off >>= 1)
            v += __shfl_xor_sync(0xffffffffu, v, off);
        if (lane == 0) s_part[wid][ci] = v;
    }
    __syncthreads();

    // per-warp gating (redundant across warps)
    float S0 = s_part[0][0] + s_part[1][0] + s_part[2][0] + s_part[3][0];
    float S1 = s_part[0][1] + s_part[1][1] + s_part[2][1] + s_part[3][1];
    float S2 = s_part[0][2] + s_part[1][2] + s_part[2][2] + s_part[3][2];
    float lg = -1e30f;
    if (lane < NE) {
        lg = (S0 * gw[lane * 23 + 0] + S1 * gw[lane * 23 + 1] +
              S2 * gw[lane * 23 + 2]) * (1.f / 256.f)
             + g_gate_pos[p * NE + lane];
    }
    float m = lg;
    #pragma unroll
    for (int off = 4; off; off >>= 1)
        m = fmaxf(m, __shfl_xor_sync(0xffffffffu, m, off));
    float pe = (lane < NE) ? expf(lg - m) : 0.f;
    float sum = pe;
    #pragma unroll
    for (int off = 4; off; off >>= 1)
        sum += __shfl_xor_sync(0xffffffffu, sum, off);
    unsigned mk = __ballot_sync(0xffffffffu, lg == m) & 0xFFu;
    int e = __ffs(mk) - 1;      // uniform across block
    if (wid == 0) {
        if (lane < NE) atomicAdd(&g_psum[lane], pe / sum);
        if (lane == 0) { g_eidx[n] = e; g_gate[n] = 1.0f / sum; }
    }

    // load expert weights transposed: sh_wT[k*8+co]
    #pragma unroll
    for (int k2 = 0; k2 < 2; k2++) {
        int idx = t + k2 * 128;
        if (idx < 216) {
            int co = idx / 27, kk = idx - co * 27;
            sh_wT[kk * 8 + co] = ew[e * 216 + idx];
        }
    }
    if (t < 8) sh_b[t] = eb[e * 8 + t];
    __syncthreads();

    // conv: thread = 2x2 pixel block x 4 output channels; ci-outer
    int cog = t >> 6;
    int pb = t & 63;
    int R = (pb >> 3) * 2, C = (pb & 7) * 2;

    float4 b4 = ((const float4*)sh_b)[cog];
    float acc[2][2][4];
    #pragma unroll
    for (int py = 0; py < 2; py++)
        #pragma unroll
        for (int px = 0; px < 2; px++) {
            acc[py][px][0] = b4.x; acc[py][px][1] = b4.y;
            acc[py][px][2] = b4.z; acc[py][px][3] = b4.w;
        }

    #pragma unroll
    for (int ci = 0; ci < 3; ci++) {
        float in_f[4][4];
        #pragma unroll
        for (int rr = 0; rr < 4; rr++) {
            const float* base = &sh_in[ci * 360 + (R + rr) * 20 + C];
            float2 u0 = *(const float2*)(base);
            float2 u1 = *(const float2*)(base + 2);
            in_f[rr][0] = u0.x; in_f[rr][1] = u0.y;
            in_f[rr][2] = u1.x; in_f[rr][3] = u1.y;
        }
        #pragma unroll
        for (int dy = 0; dy < 3; dy++)
            #pragma unroll
            for (int dx = 0; dx < 3; dx++) {
                int kk = ci * 9 + dy * 3 + dx;
                float4 w4 = ((const float4*)sh_wT)[kk * 2 + cog];
                #pragma unroll
                for (int py = 0; py < 2; py++)
                    #pragma unroll
                    for (int px = 0; px < 2; px++) {
                        float iv = in_f[dy + py][dx + px];
                        acc[py][px][0] = fmaf(w4.x, iv, acc[py][px][0]);
                        acc[py][px][1] = fmaf(w4.y, iv, acc[py][px][1]);
                        acc[py][px][2] = fmaf(w4.z, iv, acc[py][px][2]);
                        acc[py][px][3] = fmaf(w4.w, iv, acc[py][px][3]);
                    }
            }
    }

    float v[4];
    #pragma unroll
    for (int co = 0; co < 4; co++)
        v[co] = fmaxf(acc[0][0][co], 0.f) + fmaxf(acc[0][1][co], 0.f) +
                fmaxf(acc[1][0][co], 0.f) + fmaxf(acc[1][1][co], 0.f);

    // butterfly: fold co into lane bits 4,3, reduce remaining 8 lanes
    float s0, s1, o0, o1;
    if (lane & 16) { s0 = v[2]; s1 = v[3]; o0 = v[0]; o1 = v[1]; }
    else           { s0 = v[0]; s1 = v[1]; o0 = v[2]; o1 = v[3]; }
    s0 += __shfl_xor_sync(0xffffffffu, o0, 16);
    s1 += __shfl_xor_sync(0xffffffffu, o1, 16);
    float s, o;
    if (lane & 8) { s = s1; o = s0; } else { s = s0; o = s1; }
    s += __shfl_xor_sync(0xffffffffu, o, 8);
    s += __shfl_xor_sync(0xffffffffu, s, 4);
    s += __shfl_xor_sync(0xffffffffu, s, 2);
    s += __shfl_xor_sync(0xffffffffu, s, 1);
    if ((lane & 7) == 0) {
        int co = cog * 4 + ((lane >> 4) & 1) * 2 + ((lane >> 3) & 1);
        s_ws[wid][co] = s;
    }
    __syncthreads();
    if (t < 8) {
        float tot = (t < 4) ? (s_ws[0][t] + s_ws[1][t])
                            : (s_ws[2][t] + s_ws[3][t]);
        g_tok[n * 8 + t] = tot;
    }
}

// ---------------------------------------------------------------------------
// Kernel 3: rank + aux only. 1 block, 256 threads.
// ---------------------------------------------------------------------------
__global__ void rank_kernel(float* __restrict__ out, int out_size) {
    __shared__ int se[NTOK];
    int t = threadIdx.x;

    for (int i = t; i < NTOK; i += 256) se[i] = g_eidx[i];
    __syncthreads();
    int w = t >> 5, lane = t & 31;
    int base = 0;
    #pragma unroll 4
    for (int tt = 0; tt < NTOK / 32; tt++) {
        int idx = tt * 32 + lane;
        int e = se[idx];
        unsigned mask = __ballot_sync(0xffffffffu, e == w);
        if (e == w) {
            int rank = base + __popc(mask & ((1u << lane) - 1u));
            if (rank >= CCAP) g_gate[idx] = 0.f;
        }
        base += __popc(mask);
    }
    if (lane == 0) g_cnt[w] = base;
    __syncthreads();
    if (t == 0) {
        float aux = 0.f;
        #pragma unroll
        for (int e = 0; e < NE; e++) {
            float f = fminf((float)g_cnt[e], (float)CCAP) * (1.f / (float)NTOK);
            aux += f * (g_psum[e] * (1.f / (float)NTOK));
        }
        out[out_size - 1] = 8.f * aux;
    }
}

// ---------------------------------------------------------------------------
// Kernel 4: k-split classifier GEMM, 16-way k-split.
// grid (8 j-tiles, 4 batch-quads, 16 k-slices of 32) = 512 blocks x 128 thr.
// ---------------------------------------------------------------------------
__global__ void __launch_bounds__(128) linear_kernel(const float* __restrict__ lw,
                                                     float* __restrict__ out) {
    __shared__ __align__(16) float fs4[32][4];
    int bx = blockIdx.x, by = blockIdx.y, bz = blockIdx.z;
    int t = threadIdx.x;
    int k0 = bz * 32;

    {
        int kl = t & 31;
        int bq = t >> 5;
        int idx = k0 + kl;
        int co = idx >> 6;
        int cell = idx & 63;
        int py = cell >> 3, px = cell & 7;
        int bb = by * 4 + bq;
        float acc = 0.f;
        #pragma unroll
        for (int dy = 0; dy < 2; dy++)
            #pragma unroll
            for (int dx = 0; dx < 2; dx++) {
                int n = bb * 256 + (2 * py + dy) * 16 + (2 * px + dx);
                acc += g_tok[n * 8 + co] * g_gate[n];
            }
        fs4[kl][bq] = acc * (1.f / 1024.f);
    }
    __syncthreads();

    int j = bx * 128 + t;
    if (j < 1000) {
        const float* wp = lw + (size_t)k0 * 1000 + j;
        float a0 = 0.f, a1 = 0.f, a2 = 0.f, a3 = 0.f;
        #pragma unroll
        for (int k = 0; k < 32; k++) {
            float w = wp[(size_t)k * 1000];
            float4 f = *(const float4*)fs4[k];
            a0 = fmaf(w, f.x, a0);
            a1 = fmaf(w, f.y, a1);
            a2 = fmaf(w, f.z, a2);
            a3 = fmaf(w, f.w, a3);
        }
        int ob = by * 4;
        atomicAdd(&out[(ob + 0) * 1000 + j], a0);
        atomicAdd(&out[(ob + 1) * 1000 + j], a1);
        atomicAdd(&out[(ob + 2) * 1000 + j], a2);
        atomicAdd(&out[(ob + 3) * 1000 + j], a3);
    }
}

// ---------------------------------------------------------------------------
extern "C" void kernel_launch(void* const* d_in, const int* in_sizes, int n_in,
                              void* d_out, int out_size) {
    const float* X  = (const float*)d_in[0];
    const float* ew = (const float*)d_in[1];
    const float* eb = (const float*)d_in[2];
    const float* gw = (const float*)d_in[3];
    const float* gb = (const float*)d_in[4];
    const float* lw = (const float*)d_in[5];
    const float* lb = (const float*)d_in[6];
    float* out = (float*)d_out;

    init_kernel<<<96, 256>>>(gw, gb, lb, out);
    megaconv_kernel<<<NTOK, 128>>>(X, ew, eb, gw);
    rank_kernel<<<1, 256>>>(out, out_size);
    dim3 g(8, 4, 16);
    linear_kernel<<<g, 128>>>(lw, out);
}